// round 15
// baseline (speedup 1.0000x reference)
#include <cuda_runtime.h>
#include <cstdint>

// Problem constants
#define NB   32
#define C    8
#define HW   384
#define HWHW (HW*HW)
#define NX   (NB*C*HW*HW)             // 37,748,736 x elements

// Conv tile
#define TW   128
#define TH   16
#define SW   (TW+2)                   // 130
#define SH   (TH+2)                   // 18

#define AMAX_BLOCKS 2048

// ---------------- device scratch (no allocation allowed) ----------------
__device__ float g_part[AMAX_BLOCKS];  // per-block abs-max partials (all slots written)
__device__ float g_sx, g_inv;          // x scale, 1/(sx*sw)
__device__ int   g_wpk[8*9*2];         // packed int8 weights [co][tap][half]

// ---------------- K1: abs-max of x (per-block partials, no atomics) ------
__global__ void k_amax(const float4* __restrict__ x, int n4) {
    float m = 0.f;
    for (int i = blockIdx.x*blockDim.x + threadIdx.x; i < n4; i += gridDim.x*blockDim.x) {
        float4 v = x[i];
        m = fmaxf(m, fmaxf(fmaxf(fabsf(v.x), fabsf(v.y)),
                           fmaxf(fabsf(v.z), fabsf(v.w))));
    }
    #pragma unroll
    for (int o = 16; o; o >>= 1) m = fmaxf(m, __shfl_xor_sync(0xffffffffu, m, o));
    __shared__ float s[32];
    if ((threadIdx.x & 31) == 0) s[threadIdx.x >> 5] = m;
    __syncthreads();
    if (threadIdx.x < 32) {
        m = (threadIdx.x < (blockDim.x >> 5)) ? s[threadIdx.x] : 0.f;
        #pragma unroll
        for (int o = 16; o; o >>= 1) m = fmaxf(m, __shfl_xor_sync(0xffffffffu, m, o));
        if (threadIdx.x == 0) g_part[blockIdx.x] = m;
    }
}

// ---------------- K2: reduce partials, weight amax, scales, pack weights -
__global__ void k_wprep(const float* __restrict__ w) {
    __shared__ float s[32];
    __shared__ float s_ax, s_sw;
    const int tid = threadIdx.x;

    // reduce x partials (2048 -> 1)
    float m = 0.f;
    for (int i = tid; i < AMAX_BLOCKS; i += blockDim.x) m = fmaxf(m, g_part[i]);
    #pragma unroll
    for (int o = 16; o; o >>= 1) m = fmaxf(m, __shfl_xor_sync(0xffffffffu, m, o));
    if ((tid & 31) == 0) s[tid >> 5] = m;
    __syncthreads();
    if (tid == 0) {
        float ax = s[0];
        for (int i = 1; i < (int)(blockDim.x >> 5); i++) ax = fmaxf(ax, s[i]);
        s_ax = ax;
    }
    __syncthreads();

    // weight amax (576 elements)
    float mw = 0.f;
    for (int i = tid; i < 576; i += blockDim.x) mw = fmaxf(mw, fabsf(w[i]));
    #pragma unroll
    for (int o = 16; o; o >>= 1) mw = fmaxf(mw, __shfl_xor_sync(0xffffffffu, mw, o));
    if ((tid & 31) == 0) s[tid >> 5] = mw;
    __syncthreads();
    if (tid == 0) {
        float aw = s[0];
        for (int i = 1; i < (int)(blockDim.x >> 5); i++) aw = fmaxf(aw, s[i]);
        float sx = 127.0f / s_ax;
        float sw = 127.0f / aw;
        g_sx  = sx;
        g_inv = 1.0f / (sx * sw);
        s_sw  = sw;
    }
    __syncthreads();

    // pack weights: [co][tap][half], half 0 = channels 0-3, half 1 = 4-7
    float sw = s_sw;
    if (tid < 144) {
        int co = tid / 18, r = tid % 18, tap = r / 2, hf = r % 2;
        int dh = tap / 3, dw = tap % 3;
        int word = 0;
        #pragma unroll
        for (int b = 0; b < 4; b++) {
            int ci = hf * 4 + b;
            float v = w[((co * 8 + ci) * 3 + dh) * 3 + dw];
            float q = rintf(v * sw);                    // RNE == jnp.round
            q = fmaxf(-127.f, fminf(127.f, q));         // clip like reference
            int qi = (int)q;
            word |= (qi & 0xff) << (8 * b);
        }
        g_wpk[tid] = word;
    }
}

// ---------------- K3: fused quantize + int8 dp4a conv + dequant + bias ---
// grid = (3, 24, 32): 128x16 output tile per block, 256 threads.
// threads 0..127 compute co 0..3, threads 128..255 compute co 4..7,
// sharing one quantized smem input tile.
__global__ void __launch_bounds__(256, 2) k_conv(const float* __restrict__ x,
                                                 const float* __restrict__ bias,
                                                 float* __restrict__ out) {
    __shared__ uint2 sT[SH][SW];

    const int n   = blockIdx.z;
    const int ty0 = blockIdx.y * TH;
    const int tx0 = blockIdx.x * TW;
    const int tid = threadIdx.x;

    // ---- load + quantize + pack the halo tile into smem ----
    {
        const float sx = g_sx;
        const float* xb = x + (size_t)n * C * HWHW;
        for (int idx = tid; idx < SH * SW; idx += 256) {
            int r  = idx / SW, cc = idx % SW;
            int h  = ty0 + r - 1, w = tx0 + cc - 1;
            unsigned lo = 0u, hi = 0u;
            if ((unsigned)h < HW && (unsigned)w < HW) {
                const float* p = xb + (size_t)h * HW + w;
                #pragma unroll
                for (int ci = 0; ci < 8; ci++) {
                    float q = rintf(__ldg(p + (size_t)ci * HWHW) * sx);
                    q = fmaxf(-127.f, fminf(127.f, q));
                    unsigned b = (unsigned)((int)q) & 0xffu;
                    if (ci < 4) lo |= b << (8 * ci);
                    else        hi |= b << (8 * (ci - 4));
                }
            }
            sT[r][cc] = make_uint2(lo, hi);
        }
    }
    __syncthreads();

    // ---- compute: each thread owns one output column, 16 rows, 4 co ----
    const int tg  = tid >> 7;       // co group: 0 -> co 0..3, 1 -> co 4..7
    const int col = tid & 127;

    int wr[72];
    #pragma unroll
    for (int i = 0; i < 72; i++) wr[i] = g_wpk[tg * 72 + i];

    const float inv = g_inv;
    float bs[4];
    #pragma unroll
    for (int co = 0; co < 4; co++) bs[co] = __ldg(bias + tg * 4 + co);

    // sliding 3x3 window of packed pixels (uint2 = 8 channels)
    uint2 a0[3], a1[3], a2[3];
    #pragma unroll
    for (int j = 0; j < 3; j++) { a0[j] = sT[0][col + j]; a1[j] = sT[1][col + j]; }

    float* ob = out + ((size_t)n * 8 + tg * 4) * (size_t)HWHW
                    + (size_t)ty0 * HW + (tx0 + col);

    #pragma unroll
    for (int ro = 0; ro < TH; ro++) {
        #pragma unroll
        for (int j = 0; j < 3; j++) a2[j] = sT[ro + 2][col + j];

        #pragma unroll
        for (int co = 0; co < 4; co++) {
            const int* wc = wr + co * 18;
            int acc = 0;
            acc = __dp4a((int)a0[0].x, wc[0],  acc); acc = __dp4a((int)a0[0].y, wc[1],  acc);
            acc = __dp4a((int)a0[1].x, wc[2],  acc); acc = __dp4a((int)a0[1].y, wc[3],  acc);
            acc = __dp4a((int)a0[2].x, wc[4],  acc); acc = __dp4a((int)a0[2].y, wc[5],  acc);
            acc = __dp4a((int)a1[0].x, wc[6],  acc); acc = __dp4a((int)a1[0].y, wc[7],  acc);
            acc = __dp4a((int)a1[1].x, wc[8],  acc); acc = __dp4a((int)a1[1].y, wc[9],  acc);
            acc = __dp4a((int)a1[2].x, wc[10], acc); acc = __dp4a((int)a1[2].y, wc[11], acc);
            acc = __dp4a((int)a2[0].x, wc[12], acc); acc = __dp4a((int)a2[0].y, wc[13], acc);
            acc = __dp4a((int)a2[1].x, wc[14], acc); acc = __dp4a((int)a2[1].y, wc[15], acc);
            acc = __dp4a((int)a2[2].x, wc[16], acc); acc = __dp4a((int)a2[2].y, wc[17], acc);
            ob[(size_t)co * HWHW + (size_t)ro * HW] = (float)acc * inv + bs[co];
        }

        #pragma unroll
        for (int j = 0; j < 3; j++) { a0[j] = a1[j]; a1[j] = a2[j]; }
    }
}

// ---------------- launch ------------------------------------------------
extern "C" void kernel_launch(void* const* d_in, const int* in_sizes, int n_in,
                              void* d_out, int out_size) {
    const float* x    = (const float*)d_in[0];
    const float* wgt  = (const float*)d_in[1];
    const float* bias = (const float*)d_in[2];
    float* out = (float*)d_out;

    (void)in_sizes; (void)n_in; (void)out_size;

    int n4 = NX / 4;                                   // 9,437,184 float4s
    k_amax<<<AMAX_BLOCKS, 256>>>((const float4*)x, n4);

    k_wprep<<<1, 256>>>(wgt);

    dim3 cgrid(HW / TW, HW / TH, NB);                  // (3, 24, 32) = 2304 blocks
    k_conv<<<cgrid, 256>>>(x, bias, out);
}

// round 16
// speedup vs baseline: 1.0254x; 1.0254x over previous
#include <cuda_runtime.h>
#include <cstdint>

// Problem constants
#define NB   32
#define C    8
#define HW   384
#define HWHW (HW*HW)
#define NX   (NB*C*HW*HW)             // 37,748,736 x elements

// Conv tile
#define TW   128
#define TH   16
#define SW   (TW+2)                   // 130
#define SH   (TH+2)                   // 18

#define AMAX_BLOCKS 2048

// ---------------- device scratch (no allocation allowed) ----------------
__device__ float g_part[AMAX_BLOCKS];  // per-block abs-max partials (all slots written)
__device__ float g_sx, g_inv;          // x scale, 1/(sx*sw)
__device__ int   g_wpk[8*9*2];         // packed int8 weights [co][tap][half]

// ---------------- K1: abs-max of x (per-block partials, no atomics) ------
__global__ void k_amax(const float4* __restrict__ x, int n4) {
    float m = 0.f;
    for (int i = blockIdx.x*blockDim.x + threadIdx.x; i < n4; i += gridDim.x*blockDim.x) {
        float4 v = x[i];
        m = fmaxf(m, fmaxf(fmaxf(fabsf(v.x), fabsf(v.y)),
                           fmaxf(fabsf(v.z), fabsf(v.w))));
    }
    #pragma unroll
    for (int o = 16; o; o >>= 1) m = fmaxf(m, __shfl_xor_sync(0xffffffffu, m, o));
    __shared__ float s[32];
    if ((threadIdx.x & 31) == 0) s[threadIdx.x >> 5] = m;
    __syncthreads();
    if (threadIdx.x < 32) {
        m = (threadIdx.x < (blockDim.x >> 5)) ? s[threadIdx.x] : 0.f;
        #pragma unroll
        for (int o = 16; o; o >>= 1) m = fmaxf(m, __shfl_xor_sync(0xffffffffu, m, o));
        if (threadIdx.x == 0) g_part[blockIdx.x] = m;
    }
}

// ---------------- K2: reduce partials, weight amax, scales, pack weights -
__global__ void k_wprep(const float* __restrict__ w) {
    __shared__ float s[32];
    __shared__ float s_ax, s_sw;
    const int tid = threadIdx.x;

    // reduce x partials (2048 -> 1)
    float m = 0.f;
    for (int i = tid; i < AMAX_BLOCKS; i += blockDim.x) m = fmaxf(m, g_part[i]);
    #pragma unroll
    for (int o = 16; o; o >>= 1) m = fmaxf(m, __shfl_xor_sync(0xffffffffu, m, o));
    if ((tid & 31) == 0) s[tid >> 5] = m;
    __syncthreads();
    if (tid == 0) {
        float ax = s[0];
        for (int i = 1; i < (int)(blockDim.x >> 5); i++) ax = fmaxf(ax, s[i]);
        s_ax = ax;
    }
    __syncthreads();

    // weight amax (576 elements)
    float mw = 0.f;
    for (int i = tid; i < 576; i += blockDim.x) mw = fmaxf(mw, fabsf(w[i]));
    #pragma unroll
    for (int o = 16; o; o >>= 1) mw = fmaxf(mw, __shfl_xor_sync(0xffffffffu, mw, o));
    if ((tid & 31) == 0) s[tid >> 5] = mw;
    __syncthreads();
    if (tid == 0) {
        float aw = s[0];
        for (int i = 1; i < (int)(blockDim.x >> 5); i++) aw = fmaxf(aw, s[i]);
        float sx = 127.0f / s_ax;
        float sw = 127.0f / aw;
        g_sx  = sx;
        g_inv = 1.0f / (sx * sw);
        s_sw  = sw;
    }
    __syncthreads();

    // pack weights: [co][tap][half], half 0 = channels 0-3, half 1 = 4-7
    float sw = s_sw;
    if (tid < 144) {
        int co = tid / 18, r = tid % 18, tap = r / 2, hf = r % 2;
        int dh = tap / 3, dw = tap % 3;
        int word = 0;
        #pragma unroll
        for (int b = 0; b < 4; b++) {
            int ci = hf * 4 + b;
            float v = w[((co * 8 + ci) * 3 + dh) * 3 + dw];
            float q = rintf(v * sw);                    // RNE == jnp.round
            q = fmaxf(-127.f, fminf(127.f, q));         // clip like reference
            int qi = (int)q;
            word |= (qi & 0xff) << (8 * b);
        }
        g_wpk[tid] = word;
    }
}

// ---------------- K3: fused quantize + int8 dp4a conv + dequant + bias ---
// grid = (3, 24, 32): 128x16 output tile per block, 256 threads.
// threads 0..127 compute co 0..3, threads 128..255 compute co 4..7,
// sharing one quantized smem input tile.
__global__ void __launch_bounds__(256, 2) k_conv(const float* __restrict__ x,
                                                 const float* __restrict__ bias,
                                                 float* __restrict__ out) {
    __shared__ uint2 sT[SH][SW];

    const int n   = blockIdx.z;
    const int ty0 = blockIdx.y * TH;
    const int tx0 = blockIdx.x * TW;
    const int tid = threadIdx.x;

    // ---- load + quantize + pack the halo tile into smem ----
    {
        const float sx = g_sx;
        const float* xb = x + (size_t)n * C * HWHW;
        for (int idx = tid; idx < SH * SW; idx += 256) {
            int r  = idx / SW, cc = idx % SW;
            int h  = ty0 + r - 1, w = tx0 + cc - 1;
            unsigned lo = 0u, hi = 0u;
            if ((unsigned)h < HW && (unsigned)w < HW) {
                const float* p = xb + (size_t)h * HW + w;
                #pragma unroll
                for (int ci = 0; ci < 8; ci++) {
                    float q = rintf(__ldg(p + (size_t)ci * HWHW) * sx);
                    q = fmaxf(-127.f, fminf(127.f, q));
                    unsigned b = (unsigned)((int)q) & 0xffu;
                    if (ci < 4) lo |= b << (8 * ci);
                    else        hi |= b << (8 * (ci - 4));
                }
            }
            sT[r][cc] = make_uint2(lo, hi);
        }
    }
    __syncthreads();

    // ---- compute: each thread owns one output column, 16 rows, 4 co ----
    const int tg  = tid >> 7;       // co group: 0 -> co 0..3, 1 -> co 4..7
    const int col = tid & 127;

    int wr[72];
    #pragma unroll
    for (int i = 0; i < 72; i++) wr[i] = g_wpk[tg * 72 + i];

    const float inv = g_inv;
    float bs[4];
    #pragma unroll
    for (int co = 0; co < 4; co++) bs[co] = __ldg(bias + tg * 4 + co);

    // sliding 3x3 window of packed pixels (uint2 = 8 channels)
    uint2 a0[3], a1[3], a2[3];
    #pragma unroll
    for (int j = 0; j < 3; j++) { a0[j] = sT[0][col + j]; a1[j] = sT[1][col + j]; }

    float* ob = out + ((size_t)n * 8 + tg * 4) * (size_t)HWHW
                    + (size_t)ty0 * HW + (tx0 + col);

    #pragma unroll
    for (int ro = 0; ro < TH; ro++) {
        #pragma unroll
        for (int j = 0; j < 3; j++) a2[j] = sT[ro + 2][col + j];

        #pragma unroll
        for (int co = 0; co < 4; co++) {
            const int* wc = wr + co * 18;
            int acc = 0;
            acc = __dp4a((int)a0[0].x, wc[0],  acc); acc = __dp4a((int)a0[0].y, wc[1],  acc);
            acc = __dp4a((int)a0[1].x, wc[2],  acc); acc = __dp4a((int)a0[1].y, wc[3],  acc);
            acc = __dp4a((int)a0[2].x, wc[4],  acc); acc = __dp4a((int)a0[2].y, wc[5],  acc);
            acc = __dp4a((int)a1[0].x, wc[6],  acc); acc = __dp4a((int)a1[0].y, wc[7],  acc);
            acc = __dp4a((int)a1[1].x, wc[8],  acc); acc = __dp4a((int)a1[1].y, wc[9],  acc);
            acc = __dp4a((int)a1[2].x, wc[10], acc); acc = __dp4a((int)a1[2].y, wc[11], acc);
            acc = __dp4a((int)a2[0].x, wc[12], acc); acc = __dp4a((int)a2[0].y, wc[13], acc);
            acc = __dp4a((int)a2[1].x, wc[14], acc); acc = __dp4a((int)a2[1].y, wc[15], acc);
            acc = __dp4a((int)a2[2].x, wc[16], acc); acc = __dp4a((int)a2[2].y, wc[17], acc);
            ob[(size_t)co * HWHW + (size_t)ro * HW] = (float)acc * inv + bs[co];
        }

        #pragma unroll
        for (int j = 0; j < 3; j++) { a0[j] = a1[j]; a1[j] = a2[j]; }
    }
}

// ---------------- launch ------------------------------------------------
extern "C" void kernel_launch(void* const* d_in, const int* in_sizes, int n_in,
                              void* d_out, int out_size) {
    const float* x    = (const float*)d_in[0];
    const float* wgt  = (const float*)d_in[1];
    const float* bias = (const float*)d_in[2];
    float* out = (float*)d_out;

    (void)in_sizes; (void)n_in; (void)out_size;

    int n4 = NX / 4;                                   // 9,437,184 float4s
    k_amax<<<AMAX_BLOCKS, 256>>>((const float4*)x, n4);

    k_wprep<<<1, 256>>>(wgt);

    dim3 cgrid(HW / TW, HW / TH, NB);                  // (3, 24, 32) = 2304 blocks
    k_conv<<<cgrid, 256>>>(x, bias, out);
}

// round 17
// speedup vs baseline: 1.0263x; 1.0009x over previous
#include <cuda_runtime.h>
#include <cstdint>

// Problem constants
#define NB   32
#define C    8
#define HW   384
#define HWHW (HW*HW)
#define NX   (NB*C*HW*HW)             // 37,748,736 x elements

// Conv tile
#define TW   128
#define TH   16
#define SW   (TW+2)                   // 130
#define SH   (TH+2)                   // 18

#define AMAX_BLOCKS 2048

// ---------------- device scratch (no allocation allowed) ----------------
__device__ float g_part[AMAX_BLOCKS];  // per-block abs-max partials (all slots written)
__device__ float g_sx, g_inv;          // x scale, 1/(sx*sw)
__device__ int   g_wpk[8*9*2];         // packed int8 weights [co][tap][half]

// ---------------- K1: abs-max of x (per-block partials, no atomics) ------
__global__ void k_amax(const float4* __restrict__ x, int n4) {
    float m = 0.f;
    for (int i = blockIdx.x*blockDim.x + threadIdx.x; i < n4; i += gridDim.x*blockDim.x) {
        float4 v = x[i];
        m = fmaxf(m, fmaxf(fmaxf(fabsf(v.x), fabsf(v.y)),
                           fmaxf(fabsf(v.z), fabsf(v.w))));
    }
    #pragma unroll
    for (int o = 16; o; o >>= 1) m = fmaxf(m, __shfl_xor_sync(0xffffffffu, m, o));
    __shared__ float s[32];
    if ((threadIdx.x & 31) == 0) s[threadIdx.x >> 5] = m;
    __syncthreads();
    if (threadIdx.x < 32) {
        m = (threadIdx.x < (blockDim.x >> 5)) ? s[threadIdx.x] : 0.f;
        #pragma unroll
        for (int o = 16; o; o >>= 1) m = fmaxf(m, __shfl_xor_sync(0xffffffffu, m, o));
        if (threadIdx.x == 0) g_part[blockIdx.x] = m;
    }
}

// ---------------- K2: reduce partials, weight amax, scales, pack weights -
__global__ void k_wprep(const float* __restrict__ w) {
    __shared__ float s[32];
    __shared__ float s_ax, s_sw;
    const int tid = threadIdx.x;

    // reduce x partials (2048 -> 1)
    float m = 0.f;
    for (int i = tid; i < AMAX_BLOCKS; i += blockDim.x) m = fmaxf(m, g_part[i]);
    #pragma unroll
    for (int o = 16; o; o >>= 1) m = fmaxf(m, __shfl_xor_sync(0xffffffffu, m, o));
    if ((tid & 31) == 0) s[tid >> 5] = m;
    __syncthreads();
    if (tid == 0) {
        float ax = s[0];
        for (int i = 1; i < (int)(blockDim.x >> 5); i++) ax = fmaxf(ax, s[i]);
        s_ax = ax;
    }
    __syncthreads();

    // weight amax (576 elements)
    float mw = 0.f;
    for (int i = tid; i < 576; i += blockDim.x) mw = fmaxf(mw, fabsf(w[i]));
    #pragma unroll
    for (int o = 16; o; o >>= 1) mw = fmaxf(mw, __shfl_xor_sync(0xffffffffu, mw, o));
    if ((tid & 31) == 0) s[tid >> 5] = mw;
    __syncthreads();
    if (tid == 0) {
        float aw = s[0];
        for (int i = 1; i < (int)(blockDim.x >> 5); i++) aw = fmaxf(aw, s[i]);
        float sx = 127.0f / s_ax;
        float sw = 127.0f / aw;
        g_sx  = sx;
        g_inv = 1.0f / (sx * sw);
        s_sw  = sw;
    }
    __syncthreads();

    // pack weights: [co][tap][half], half 0 = channels 0-3, half 1 = 4-7
    float sw = s_sw;
    if (tid < 144) {
        int co = tid / 18, r = tid % 18, tap = r / 2, hf = r % 2;
        int dh = tap / 3, dw = tap % 3;
        int word = 0;
        #pragma unroll
        for (int b = 0; b < 4; b++) {
            int ci = hf * 4 + b;
            float v = w[((co * 8 + ci) * 3 + dh) * 3 + dw];
            float q = rintf(v * sw);                    // RNE == jnp.round
            q = fmaxf(-127.f, fminf(127.f, q));         // clip like reference
            int qi = (int)q;
            word |= (qi & 0xff) << (8 * b);
        }
        g_wpk[tid] = word;
    }
}

// ---------------- K3: fused quantize + int8 dp4a conv + dequant + bias ---
// grid = (3, 24, 32): 128x16 output tile per block, 256 threads.
// threads 0..127 compute co 0..3, threads 128..255 compute co 4..7,
// sharing one quantized smem input tile.
__global__ void __launch_bounds__(256, 2) k_conv(const float* __restrict__ x,
                                                 const float* __restrict__ bias,
                                                 float* __restrict__ out) {
    __shared__ uint2 sT[SH][SW];

    const int n   = blockIdx.z;
    const int ty0 = blockIdx.y * TH;
    const int tx0 = blockIdx.x * TW;
    const int tid = threadIdx.x;

    // ---- load + quantize + pack the halo tile into smem ----
    {
        const float sx = g_sx;
        const float* xb = x + (size_t)n * C * HWHW;
        for (int idx = tid; idx < SH * SW; idx += 256) {
            int r  = idx / SW, cc = idx % SW;
            int h  = ty0 + r - 1, w = tx0 + cc - 1;
            unsigned lo = 0u, hi = 0u;
            if ((unsigned)h < HW && (unsigned)w < HW) {
                const float* p = xb + (size_t)h * HW + w;
                #pragma unroll
                for (int ci = 0; ci < 8; ci++) {
                    float q = rintf(__ldg(p + (size_t)ci * HWHW) * sx);
                    q = fmaxf(-127.f, fminf(127.f, q));
                    unsigned b = (unsigned)((int)q) & 0xffu;
                    if (ci < 4) lo |= b << (8 * ci);
                    else        hi |= b << (8 * (ci - 4));
                }
            }
            sT[r][cc] = make_uint2(lo, hi);
        }
    }
    __syncthreads();

    // ---- compute: each thread owns one output column, 16 rows, 4 co ----
    const int tg  = tid >> 7;       // co group: 0 -> co 0..3, 1 -> co 4..7
    const int col = tid & 127;

    int wr[72];
    #pragma unroll
    for (int i = 0; i < 72; i++) wr[i] = g_wpk[tg * 72 + i];

    const float inv = g_inv;
    float bs[4];
    #pragma unroll
    for (int co = 0; co < 4; co++) bs[co] = __ldg(bias + tg * 4 + co);

    // sliding 3x3 window of packed pixels (uint2 = 8 channels)
    uint2 a0[3], a1[3], a2[3];
    #pragma unroll
    for (int j = 0; j < 3; j++) { a0[j] = sT[0][col + j]; a1[j] = sT[1][col + j]; }

    float* ob = out + ((size_t)n * 8 + tg * 4) * (size_t)HWHW
                    + (size_t)ty0 * HW + (tx0 + col);

    #pragma unroll
    for (int ro = 0; ro < TH; ro++) {
        #pragma unroll
        for (int j = 0; j < 3; j++) a2[j] = sT[ro + 2][col + j];

        #pragma unroll
        for (int co = 0; co < 4; co++) {
            const int* wc = wr + co * 18;
            int acc = 0;
            acc = __dp4a((int)a0[0].x, wc[0],  acc); acc = __dp4a((int)a0[0].y, wc[1],  acc);
            acc = __dp4a((int)a0[1].x, wc[2],  acc); acc = __dp4a((int)a0[1].y, wc[3],  acc);
            acc = __dp4a((int)a0[2].x, wc[4],  acc); acc = __dp4a((int)a0[2].y, wc[5],  acc);
            acc = __dp4a((int)a1[0].x, wc[6],  acc); acc = __dp4a((int)a1[0].y, wc[7],  acc);
            acc = __dp4a((int)a1[1].x, wc[8],  acc); acc = __dp4a((int)a1[1].y, wc[9],  acc);
            acc = __dp4a((int)a1[2].x, wc[10], acc); acc = __dp4a((int)a1[2].y, wc[11], acc);
            acc = __dp4a((int)a2[0].x, wc[12], acc); acc = __dp4a((int)a2[0].y, wc[13], acc);
            acc = __dp4a((int)a2[1].x, wc[14], acc); acc = __dp4a((int)a2[1].y, wc[15], acc);
            acc = __dp4a((int)a2[2].x, wc[16], acc); acc = __dp4a((int)a2[2].y, wc[17], acc);
            ob[(size_t)co * HWHW + (size_t)ro * HW] = (float)acc * inv + bs[co];
        }

        #pragma unroll
        for (int j = 0; j < 3; j++) { a0[j] = a1[j]; a1[j] = a2[j]; }
    }
}

// ---------------- launch ------------------------------------------------
extern "C" void kernel_launch(void* const* d_in, const int* in_sizes, int n_in,
                              void* d_out, int out_size) {
    const float* x    = (const float*)d_in[0];
    const float* wgt  = (const float*)d_in[1];
    const float* bias = (const float*)d_in[2];
    float* out = (float*)d_out;

    (void)in_sizes; (void)n_in; (void)out_size;

    int n4 = NX / 4;                                   // 9,437,184 float4s
    k_amax<<<AMAX_BLOCKS, 256>>>((const float4*)x, n4);

    k_wprep<<<1, 256>>>(wgt);

    dim3 cgrid(HW / TW, HW / TH, NB);                  // (3, 24, 32) = 2304 blocks
    k_conv<<<cgrid, 256>>>(x, bias, out);
}